// round 8
// baseline (speedup 1.0000x reference)
#include <cuda_runtime.h>
#include <cuda_fp16.h>
#include <mma.h>
#include <cstdint>
#include <cstddef>

using namespace nvcuda;
namespace wx = nvcuda::wmma;

#define NB 256
#define HD 1024
#define DD 256
#define TT 128

// ---- persistent step kernel geometry (R5: 8 warps, warp tile 32x32) ----
#define NTHR 256
#define KT2 64                    // k per chunk
#define NCH (HD / KT2)            // 16 chunks
#define LDA 72                    // A smem row stride (halves)
#define LDB 1032                  // B smem row stride (halves)
#define STGA (128 * LDA)          // halves per A stage (9216)
#define SMB_OFF (3 * STGA)
#define PERS_SMEM ((3 * STGA + 64 * LDB) * 2)   // 187392 B
#define LDG 68                    // gates smem row stride (floats); aliases A stages

// ---- fc kernel geometry ----
#define KT 32
#define NC (HD / KT)
#define LDTH 40
#define STG_A (128 * LDTH)
#define STG_B (64 * LDTH)
#define STG_H (STG_A + STG_B)
#define FC_SMEM (3 * STG_H * 2)

// ---------------- static device scratch ----------------
__device__ __half g_Wc[4096 * HD];              // gate-permuted (Wih+Whh)  8 MB
__device__ __half g_Wp[4096 * HD];              // gate-permuted Wih        8 MB
__device__ __half g_Wfc[DD * HD];
__device__ __half g_x0[NB * HD];
__device__ float  g_bp[4096];
__device__ __half g_h[(size_t)TT * NB * HD];    // hidden history fp16 (64 MB)
__device__ unsigned g_cnt[TT * 2 * 16];         // dataflow flags [t][by][kchunk]

__device__ __forceinline__ float sigm(float z) { return 1.0f / (1.0f + __expf(-z)); }

#define CP16(saddr, gptr) \
    asm volatile("cp.async.cg.shared.global [%0], [%1], 16;" :: "r"(saddr), "l"(gptr) : "memory")
#define CP_COMMIT() asm volatile("cp.async.commit_group;" ::: "memory")

// ---------------- prep ----------------
__global__ void prep_kernel(const float* __restrict__ Wih, const float* __restrict__ Whh,
                            const float* __restrict__ bih, const float* __restrict__ bhh,
                            const float* __restrict__ Wfc, const float* __restrict__ hT) {
    size_t idx = (size_t)blockIdx.x * 256 + threadIdx.x;
    if (idx < (size_t)4096 * HD) {
        int k = (int)(idx & (HD - 1));
        int rowp = (int)(idx >> 10);            // permuted gate row: j*4 + G
        int j = rowp >> 2, G = rowp & 3;
        size_t src = (size_t)(G * HD + j) * HD + k;
        float a = Wih[src];
        g_Wp[idx] = __float2half_rn(a);
        g_Wc[idx] = __float2half_rn(a + Whh[src]);
    }
    if (idx < (size_t)DD * HD) g_Wfc[idx] = __float2half_rn(Wfc[idx]);
    if (idx < (size_t)NB * HD) g_x0[idx] = __float2half_rn(hT[idx]);
    if (idx < 4096) {
        int j = (int)(idx >> 2), G = (int)(idx & 3);
        g_bp[idx] = bih[G * HD + j] + bhh[G * HD + j];
        g_cnt[idx] = 0u;                        // reset dataflow flags each launch
    }
}

// ---------------- persistent LSTM with single-thread dataflow gates ----------------
// grid (64, 2): n0 = bx*64 permuted gate cols (16 units), m0 = by*128 batch rows.
// 8 warps; warp tile 32x32. B resident in smem; c in registers. No global barrier:
// A-chunk kc of step t gated on counter[t-1][by][kc] == 4 (its 4 producer CTAs),
// spin by thread 0 only, broadcast via one __syncthreads.
__global__ void __launch_bounds__(NTHR) lstm_persist() {
    extern __shared__ __half smh[];
    __half* smB = smh + SMB_OFF;
    float* gates = (float*)smh;                 // aliases A stages between steps

    const int tid = (int)threadIdx.x;
    const int w = tid >> 5;
    const int wm0 = (w & 3) * 32;
    const int wn0 = (w >> 2) * 32;
    const int bx = (int)blockIdx.x;
    const int by = (int)blockIdx.y;
    const size_t n0 = (size_t)bx * 64;
    const size_t m0 = (size_t)by * 128;

    const int ur = tid & 3;                     // unit quad
    const int rr = tid >> 2;                    // 0..63
    const int j0 = (int)(n0 >> 2);              // global hidden-unit base

    auto loadB = [&](const __half* __restrict__ Wsrc) {
        uint32_t sB = (uint32_t)__cvta_generic_to_shared(smB);
#pragma unroll
        for (int i = 0; i < 32; ++i) {
            int p = tid + i * NTHR;             // 0..8191
            int r = p >> 7;
            int sg = p & 127;
            CP16(sB + (uint32_t)(r * LDB + sg * 8) * 2u, Wsrc + (n0 + (size_t)r) * HD + sg * 8);
        }
        CP_COMMIT();
    };

    loadB(g_Wp);
    asm volatile("cp.async.wait_group 0;" ::: "memory");
    __syncthreads();

    float4 bq[4];
#pragma unroll
    for (int q = 0; q < 4; ++q)
        bq[q] = *(const float4*)(g_bp + n0 + (ur * 4 + q) * 4);

    float creg[8];
#pragma unroll
    for (int i = 0; i < 8; ++i) creg[i] = 0.0f;

    for (int t = 0; t < TT; ++t) {
        const __half* A = (t == 0) ? g_x0 : (g_h + (size_t)(t - 1) * NB * HD);

        // gate: thread 0 spins until the 4 producers of A-chunk kc published h[t-1]
        auto gate = [&](int kc) {
            if (t == 0) return;
            if (tid == 0) {
                const unsigned* f = g_cnt + ((t - 1) * 2 + by) * 16 + kc;
                unsigned v;
                int spins = 0;
                while (true) {
                    asm volatile("ld.acquire.gpu.global.u32 %0, [%1];" : "=r"(v) : "l"(f));
                    if (v >= 4u) break;
                    if (++spins > 64) __nanosleep(32);
                }
            }
            __syncthreads();
        };

        auto loadA = [&](int kc) {
            uint32_t sA = (uint32_t)__cvta_generic_to_shared(smh + (kc % 3) * STGA);
            const __half* gA = A + m0 * HD + (size_t)kc * KT2;
#pragma unroll
            for (int i = 0; i < 4; ++i) {
                int p = tid + i * NTHR;         // 0..1023
                int r = p >> 3;
                int sg = p & 7;
                CP16(sA + (uint32_t)(r * LDA + sg * 8) * 2u, gA + (size_t)r * HD + sg * 8);
            }
            CP_COMMIT();
        };

        wx::fragment<wx::accumulator, 16, 16, 16, float> cf[2][2];
#pragma unroll
        for (int i = 0; i < 2; ++i)
#pragma unroll
            for (int j = 0; j < 2; ++j) wx::fill_fragment(cf[i][j], 0.0f);

        gate(0); loadA(0);
        gate(1); loadA(1);

        for (int kc = 0; kc < NCH; ++kc) {
            if (kc < NCH - 1) asm volatile("cp.async.wait_group 1;" ::: "memory");
            else              asm volatile("cp.async.wait_group 0;" ::: "memory");
            __syncthreads();
            if (kc + 2 < NCH) { gate(kc + 2); loadA(kc + 2); }

            const __half* smA = smh + (kc % 3) * STGA;
#pragma unroll
            for (int ks = 0; ks < 4; ++ks) {
                wx::fragment<wx::matrix_a, 16, 16, 16, __half, wx::row_major> af[2];
                wx::fragment<wx::matrix_b, 16, 16, 16, __half, wx::col_major> bf[2];
#pragma unroll
                for (int i = 0; i < 2; ++i)
                    wx::load_matrix_sync(af[i], smA + (wm0 + i * 16) * LDA + ks * 16, LDA);
#pragma unroll
                for (int j = 0; j < 2; ++j)
                    wx::load_matrix_sync(bf[j], smB + (wn0 + j * 16) * LDB + kc * KT2 + ks * 16, LDB);
#pragma unroll
                for (int i = 0; i < 2; ++i)
#pragma unroll
                    for (int j = 0; j < 2; ++j)
                        wx::mma_sync(cf[i][j], af[i], bf[j], cf[i][j]);
            }
        }

        __syncthreads();     // A stages free; alias as gates
#pragma unroll
        for (int i = 0; i < 2; ++i)
#pragma unroll
            for (int j = 0; j < 2; ++j)
                wx::store_matrix_sync(gates + (wm0 + i * 16) * LDG + wn0 + j * 16,
                                      cf[i][j], LDG, wx::mem_row_major);
        __syncthreads();

        // swap in combined weights after step 0 (overlaps epilogue)
        if (t == 0) loadB(g_Wc);

        // pointwise epilogue; c stays in registers
        __half* hbase = g_h + (size_t)t * NB * HD;
#pragma unroll
        for (int p = 0; p < 2; ++p) {
            int r = rr + p * 64;
            size_t m = m0 + r;
            __half hv[4];
#pragma unroll
            for (int q = 0; q < 4; ++q) {
                float4 gv = *(const float4*)(gates + r * LDG + (ur * 4 + q) * 4);
                const float* bb = &bq[q].x;
                float iv = sigm(gv.x + bb[0]);
                float fv = sigm(gv.y + bb[1]);
                float gg = tanhf(gv.z + bb[2]);
                float ov = sigm(gv.w + bb[3]);
                float c = fmaf(fv, creg[p * 4 + q], iv * gg);
                creg[p * 4 + q] = c;
                hv[q] = __float2half_rn(ov * tanhf(c));
            }
            *(uint2*)(hbase + m * HD + j0 + ur * 4) = *(uint2*)hv;
        }

        if (t == 0) asm volatile("cp.async.wait_group 0;" ::: "memory");  // retire B swap

        // publish h[t]: this CTA produced cols [16bx,16bx+16) -> chunk bx>>2.
        // syncthreads makes all threads' h stores visible to tid0; release-red is cumulative.
        __syncthreads();
        if (tid == 0) {
            unsigned* f = g_cnt + (t * 2 + by) * 16 + (bx >> 2);
            asm volatile("red.release.gpu.global.add.u32 [%0], %1;" :: "l"(f), "r"(1u) : "memory");
        }
        // no trailing barrier: next step's gate(0) provides ordering; the syncthreads
        // above also protects the gates smem (aliased A stage 0) from early overwrite.
    }
}

// ---------------- FC: out[32768,256] = h @ Wfc^T + b ----------------
__device__ __forceinline__ void gemm16_fc(const __half* __restrict__ A, size_t m0,
                                          const __half* __restrict__ B, size_t n0,
                                          __half* smh, float* gates) {
    const int tid = (int)threadIdx.x;
    const int w = tid >> 5;
    const int wm0 = (w & 3) * 32;
    const int wn0 = (w >> 2) * 32;

    wx::fragment<wx::accumulator, 16, 16, 16, float> cf[2][2];
#pragma unroll
    for (int i = 0; i < 2; ++i)
#pragma unroll
        for (int j = 0; j < 2; ++j) wx::fill_fragment(cf[i][j], 0.0f);

    auto load_chunk = [&](int kc) {
        __half* smA = smh + (kc % 3) * STG_H;
        __half* smB = smA + STG_A;
        uint32_t sA = (uint32_t)__cvta_generic_to_shared(smA);
        uint32_t sB = (uint32_t)__cvta_generic_to_shared(smB);
        const __half* gA = A + m0 * HD + (size_t)kc * KT;
        const __half* gB = B + n0 * HD + (size_t)kc * KT;
#pragma unroll
        for (int i = 0; i < 2; ++i) {
            int p = tid + i * 256;
            int r = p >> 2, seg = p & 3;
            CP16(sA + (uint32_t)(r * LDTH + seg * 8) * 2u, gA + (size_t)r * HD + seg * 8);
        }
        {
            int r = tid >> 2, seg = tid & 3;
            CP16(sB + (uint32_t)(r * LDTH + seg * 8) * 2u, gB + (size_t)r * HD + seg * 8);
        }
        CP_COMMIT();
    };

    load_chunk(0);
    load_chunk(1);

    for (int kc = 0; kc < NC; ++kc) {
        if (kc < NC - 1) asm volatile("cp.async.wait_group 1;" ::: "memory");
        else             asm volatile("cp.async.wait_group 0;" ::: "memory");
        __syncthreads();
        if (kc + 2 < NC) load_chunk(kc + 2);

        __half* smA = smh + (kc % 3) * STG_H;
        __half* smB = smA + STG_A;
#pragma unroll
        for (int ks = 0; ks < 2; ++ks) {
            wx::fragment<wx::matrix_a, 16, 16, 16, __half, wx::row_major> af[2];
            wx::fragment<wx::matrix_b, 16, 16, 16, __half, wx::col_major> bf[2];
#pragma unroll
            for (int i = 0; i < 2; ++i)
                wx::load_matrix_sync(af[i], smA + (wm0 + i * 16) * LDTH + ks * 16, LDTH);
#pragma unroll
            for (int j = 0; j < 2; ++j)
                wx::load_matrix_sync(bf[j], smB + (wn0 + j * 16) * LDTH + ks * 16, LDTH);
#pragma unroll
            for (int i = 0; i < 2; ++i)
#pragma unroll
                for (int j = 0; j < 2; ++j)
                    wx::mma_sync(cf[i][j], af[i], bf[j], cf[i][j]);
        }
    }

    __syncthreads();
#pragma unroll
    for (int i = 0; i < 2; ++i)
#pragma unroll
        for (int j = 0; j < 2; ++j)
            wx::store_matrix_sync(gates + (wm0 + i * 16) * LDG + wn0 + j * 16,
                                  cf[i][j], LDG, wx::mem_row_major);
    __syncthreads();
}

__global__ void __launch_bounds__(256) fc_kernel(const float* __restrict__ bfc,
                                                 float* __restrict__ out) {
    extern __shared__ __half smh[];
    float* gates = (float*)smh;
    size_t n0 = (size_t)blockIdx.x * 64;
    size_t m0 = (size_t)blockIdx.y * 128;

    gemm16_fc(g_h, m0, g_Wfc, n0, smh, gates);

    const int tid = (int)threadIdx.x;
    const int cg = tid & 3;
    const int rr = tid >> 2;
#pragma unroll
    for (int p = 0; p < 2; ++p) {
        int r = rr + p * 64;
        size_t m = m0 + r;
#pragma unroll
        for (int q = 0; q < 4; ++q) {
            int c = cg * 16 + q * 4;
            float4 gv = *(const float4*)(gates + r * LDG + c);
            float4 bv = *(const float4*)(bfc + n0 + c);
            gv.x += bv.x; gv.y += bv.y; gv.z += bv.z; gv.w += bv.w;
            *(float4*)(out + m * DD + n0 + c) = gv;
        }
    }
}

// ---------------- launch ----------------
extern "C" void kernel_launch(void* const* d_in, const int* in_sizes, int n_in,
                              void* d_out, int out_size) {
    const float* hT  = (const float*)d_in[0];
    // d_in[1] = t (int32) — fixed 128 for this problem
    const float* Wih = (const float*)d_in[2];
    const float* Whh = (const float*)d_in[3];
    const float* bih = (const float*)d_in[4];
    const float* bhh = (const float*)d_in[5];
    const float* Wfc = (const float*)d_in[6];
    const float* bfc = (const float*)d_in[7];
    float* out = (float*)d_out;

    cudaFuncSetAttribute(lstm_persist, cudaFuncAttributeMaxDynamicSharedMemorySize, PERS_SMEM);
    cudaFuncSetAttribute(fc_kernel, cudaFuncAttributeMaxDynamicSharedMemorySize, FC_SMEM);

    prep_kernel<<<(4096 * HD) / 256, 256>>>(Wih, Whh, bih, bhh, Wfc, hT);

    lstm_persist<<<dim3(64, 2), NTHR, PERS_SMEM>>>();

    fc_kernel<<<dim3(4, 256), 256, FC_SMEM>>>(bfc, out);
}

// round 9
// speedup vs baseline: 1.3158x; 1.3158x over previous
#include <cuda_runtime.h>
#include <cuda_fp16.h>
#include <mma.h>
#include <cstdint>
#include <cstddef>

using namespace nvcuda;
namespace wx = nvcuda::wmma;

#define NB 256
#define HD 1024
#define DD 256
#define TT 128

// ---- persistent step kernel geometry (8 warps, warp tile 32x32) ----
#define NTHR 256
#define KT2 64                    // k per chunk
#define NCH (HD / KT2)            // 16 chunks
#define LDA 72                    // A smem row stride (halves)
#define LDB 1032                  // B smem row stride (halves)
#define STGA (128 * LDA)          // halves per A stage (9216)
#define SMB_OFF (3 * STGA)
#define PERS_SMEM ((3 * STGA + 64 * LDB) * 2)   // 187392 B
#define LDG 68                    // gates smem row stride (floats); aliases A stages

// ---- fc kernel geometry ----
#define KT 32
#define NC (HD / KT)
#define LDTH 40
#define STG_A (128 * LDTH)
#define STG_B (64 * LDTH)
#define STG_H (STG_A + STG_B)
#define FC_SMEM (3 * STG_H * 2)

// ---------------- static device scratch ----------------
__device__ __half g_Wc[4096 * HD];              // gate-permuted (Wih+Whh)  8 MB
__device__ __half g_Wp[4096 * HD];              // gate-permuted Wih        8 MB
__device__ __half g_Wfc[DD * HD];
__device__ __half g_x0[NB * HD];
__device__ float  g_bp[4096];
__device__ __half g_h[(size_t)TT * NB * HD];    // hidden history fp16 (64 MB)
__device__ unsigned g_barcnt[64];               // per-half counters at [by*32]
__device__ volatile unsigned g_bargen[64];      // per-half generation at [by*32]

// fast pointwise: sigma(z) = 1/(1+e^-z), tanh(z) = 2*sigma(2z)-1, via MUFU paths
__device__ __forceinline__ float sigm(float z) {
    return __fdividef(1.0f, 1.0f + __expf(-z));
}
__device__ __forceinline__ float ftanh(float z) {
    return __fdividef(2.0f, 1.0f + __expf(-2.0f * z)) - 1.0f;
}

#define CP16(saddr, gptr) \
    asm volatile("cp.async.cg.shared.global [%0], [%1], 16;" :: "r"(saddr), "l"(gptr) : "memory")
#define CP_COMMIT() asm volatile("cp.async.commit_group;" ::: "memory")

// barrier over the 64 CTAs sharing one batch half (the two halves are independent)
__device__ __forceinline__ void half_barrier(int by) {
    __syncthreads();
    if (threadIdx.x == 0) {
        __threadfence();
        unsigned g = g_bargen[by * 32];
        if (atomicAdd(&g_barcnt[by * 32], 1u) == 63u) {
            g_barcnt[by * 32] = 0;
            __threadfence();
            g_bargen[by * 32] = g + 1;
        } else {
            while (g_bargen[by * 32] == g) { }
        }
    }
    __syncthreads();
}

// ---------------- prep ----------------
__global__ void prep_kernel(const float* __restrict__ Wih, const float* __restrict__ Whh,
                            const float* __restrict__ bih, const float* __restrict__ bhh,
                            const float* __restrict__ Wfc, const float* __restrict__ hT) {
    size_t idx = (size_t)blockIdx.x * 256 + threadIdx.x;
    if (idx < (size_t)4096 * HD) {
        int k = (int)(idx & (HD - 1));
        int rowp = (int)(idx >> 10);            // permuted gate row: j*4 + G
        int j = rowp >> 2, G = rowp & 3;
        size_t src = (size_t)(G * HD + j) * HD + k;
        float a = Wih[src];
        g_Wp[idx] = __float2half_rn(a);
        g_Wc[idx] = __float2half_rn(a + Whh[src]);
    }
    if (idx < (size_t)DD * HD) g_Wfc[idx] = __float2half_rn(Wfc[idx]);
    if (idx < (size_t)NB * HD) g_x0[idx] = __float2half_rn(hT[idx]);
    if (idx < 4096) {
        int j = (int)(idx >> 2), G = (int)(idx & 3);
        g_bp[idx] = bih[G * HD + j] + bhh[G * HD + j];
    }
    if (idx < 64) { g_barcnt[idx] = 0u; *(unsigned*)&g_bargen[idx] = 0u; }
}

// ---------------- persistent LSTM ----------------
// grid (64, 2): n0 = bx*64 permuted gate cols (16 units), m0 = by*128 batch rows.
// 8 warps, warp tile 32x32. B resident in smem; c in registers; per-half barrier.
__global__ void __launch_bounds__(NTHR) lstm_persist() {
    extern __shared__ __half smh[];
    __half* smB = smh + SMB_OFF;
    float* gates = (float*)smh;                 // aliases A stages between steps

    const int tid = (int)threadIdx.x;
    const int w = tid >> 5;
    const int wm0 = (w & 3) * 32;
    const int wn0 = (w >> 2) * 32;
    const int by = (int)blockIdx.y;
    const size_t n0 = (size_t)blockIdx.x * 64;
    const size_t m0 = (size_t)by * 128;

    const int ur = tid & 3;                     // unit quad
    const int rr = tid >> 2;                    // 0..63
    const int j0 = (int)(n0 >> 2);              // global hidden-unit base

    auto loadB = [&](const __half* __restrict__ Wsrc) {
        uint32_t sB = (uint32_t)__cvta_generic_to_shared(smB);
#pragma unroll
        for (int i = 0; i < 32; ++i) {
            int p = tid + i * NTHR;             // 0..8191
            int r = p >> 7;
            int sg = p & 127;
            CP16(sB + (uint32_t)(r * LDB + sg * 8) * 2u, Wsrc + (n0 + (size_t)r) * HD + sg * 8);
        }
        CP_COMMIT();
    };

    loadB(g_Wp);
    asm volatile("cp.async.wait_group 0;" ::: "memory");
    __syncthreads();

    float4 bq[4];
#pragma unroll
    for (int q = 0; q < 4; ++q)
        bq[q] = *(const float4*)(g_bp + n0 + (ur * 4 + q) * 4);

    float creg[8];
#pragma unroll
    for (int i = 0; i < 8; ++i) creg[i] = 0.0f;

    for (int t = 0; t < TT; ++t) {
        const __half* A = (t == 0) ? g_x0 : (g_h + (size_t)(t - 1) * NB * HD);

        auto loadA = [&](int kc) {
            uint32_t sA = (uint32_t)__cvta_generic_to_shared(smh + (kc % 3) * STGA);
            const __half* gA = A + m0 * HD + (size_t)kc * KT2;
#pragma unroll
            for (int i = 0; i < 4; ++i) {
                int p = tid + i * NTHR;         // 0..1023
                int r = p >> 3;
                int sg = p & 7;
                CP16(sA + (uint32_t)(r * LDA + sg * 8) * 2u, gA + (size_t)r * HD + sg * 8);
            }
            CP_COMMIT();
        };

        wx::fragment<wx::accumulator, 16, 16, 16, float> cf[2][2];
#pragma unroll
        for (int i = 0; i < 2; ++i)
#pragma unroll
            for (int j = 0; j < 2; ++j) wx::fill_fragment(cf[i][j], 0.0f);

        loadA(0);
        loadA(1);

        for (int kc = 0; kc < NCH; ++kc) {
            if (kc < NCH - 1) asm volatile("cp.async.wait_group 1;" ::: "memory");
            else              asm volatile("cp.async.wait_group 0;" ::: "memory");
            __syncthreads();
            if (kc + 2 < NCH) loadA(kc + 2);

            const __half* smA = smh + (kc % 3) * STGA;
#pragma unroll
            for (int ks = 0; ks < 4; ++ks) {
                wx::fragment<wx::matrix_a, 16, 16, 16, __half, wx::row_major> af[2];
                wx::fragment<wx::matrix_b, 16, 16, 16, __half, wx::col_major> bf[2];
#pragma unroll
                for (int i = 0; i < 2; ++i)
                    wx::load_matrix_sync(af[i], smA + (wm0 + i * 16) * LDA + ks * 16, LDA);
#pragma unroll
                for (int j = 0; j < 2; ++j)
                    wx::load_matrix_sync(bf[j], smB + (wn0 + j * 16) * LDB + kc * KT2 + ks * 16, LDB);
#pragma unroll
                for (int i = 0; i < 2; ++i)
#pragma unroll
                    for (int j = 0; j < 2; ++j)
                        wx::mma_sync(cf[i][j], af[i], bf[j], cf[i][j]);
            }
        }

        __syncthreads();     // A stages free; alias as gates
#pragma unroll
        for (int i = 0; i < 2; ++i)
#pragma unroll
            for (int j = 0; j < 2; ++j)
                wx::store_matrix_sync(gates + (wm0 + i * 16) * LDG + wn0 + j * 16,
                                      cf[i][j], LDG, wx::mem_row_major);
        __syncthreads();

        // swap in combined weights after step 0 (overlaps epilogue)
        if (t == 0) loadB(g_Wc);

        // pointwise epilogue; c stays in registers
        __half* hbase = g_h + (size_t)t * NB * HD;
#pragma unroll
        for (int p = 0; p < 2; ++p) {
            int r = rr + p * 64;
            size_t m = m0 + r;
            __half hv[4];
#pragma unroll
            for (int q = 0; q < 4; ++q) {
                float4 gv = *(const float4*)(gates + r * LDG + (ur * 4 + q) * 4);
                const float* bb = &bq[q].x;
                float iv = sigm(gv.x + bb[0]);
                float fv = sigm(gv.y + bb[1]);
                float gg = ftanh(gv.z + bb[2]);
                float ov = sigm(gv.w + bb[3]);
                float c = fmaf(fv, creg[p * 4 + q], iv * gg);
                creg[p * 4 + q] = c;
                hv[q] = __float2half_rn(ov * ftanh(c));
            }
            *(uint2*)(hbase + m * HD + j0 + ur * 4) = *(uint2*)hv;
        }

        if (t == 0) asm volatile("cp.async.wait_group 0;" ::: "memory");  // retire B swap

        half_barrier(by);    // h[t] of this batch half visible to its 64 CTAs
    }
}

// ---------------- FC: out[32768,256] = h @ Wfc^T + b ----------------
__device__ __forceinline__ void gemm16_fc(const __half* __restrict__ A, size_t m0,
                                          const __half* __restrict__ B, size_t n0,
                                          __half* smh, float* gates) {
    const int tid = (int)threadIdx.x;
    const int w = tid >> 5;
    const int wm0 = (w & 3) * 32;
    const int wn0 = (w >> 2) * 32;

    wx::fragment<wx::accumulator, 16, 16, 16, float> cf[2][2];
#pragma unroll
    for (int i = 0; i < 2; ++i)
#pragma unroll
        for (int j = 0; j < 2; ++j) wx::fill_fragment(cf[i][j], 0.0f);

    auto load_chunk = [&](int kc) {
        __half* smA = smh + (kc % 3) * STG_H;
        __half* smB = smA + STG_A;
        uint32_t sA = (uint32_t)__cvta_generic_to_shared(smA);
        uint32_t sB = (uint32_t)__cvta_generic_to_shared(smB);
        const __half* gA = A + m0 * HD + (size_t)kc * KT;
        const __half* gB = B + n0 * HD + (size_t)kc * KT;
#pragma unroll
        for (int i = 0; i < 2; ++i) {
            int p = tid + i * 256;
            int r = p >> 2, seg = p & 3;
            CP16(sA + (uint32_t)(r * LDTH + seg * 8) * 2u, gA + (size_t)r * HD + seg * 8);
        }
        {
            int r = tid >> 2, seg = tid & 3;
            CP16(sB + (uint32_t)(r * LDTH + seg * 8) * 2u, gB + (size_t)r * HD + seg * 8);
        }
        CP_COMMIT();
    };

    load_chunk(0);
    load_chunk(1);

    for (int kc = 0; kc < NC; ++kc) {
        if (kc < NC - 1) asm volatile("cp.async.wait_group 1;" ::: "memory");
        else             asm volatile("cp.async.wait_group 0;" ::: "memory");
        __syncthreads();
        if (kc + 2 < NC) load_chunk(kc + 2);

        __half* smA = smh + (kc % 3) * STG_H;
        __half* smB = smA + STG_A;
#pragma unroll
        for (int ks = 0; ks < 2; ++ks) {
            wx::fragment<wx::matrix_a, 16, 16, 16, __half, wx::row_major> af[2];
            wx::fragment<wx::matrix_b, 16, 16, 16, __half, wx::col_major> bf[2];
#pragma unroll
            for (int i = 0; i < 2; ++i)
                wx::load_matrix_sync(af[i], smA + (wm0 + i * 16) * LDTH + ks * 16, LDTH);
#pragma unroll
            for (int j = 0; j < 2; ++j)
                wx::load_matrix_sync(bf[j], smB + (wn0 + j * 16) * LDTH + ks * 16, LDTH);
#pragma unroll
            for (int i = 0; i < 2; ++i)
#pragma unroll
                for (int j = 0; j < 2; ++j)
                    wx::mma_sync(cf[i][j], af[i], bf[j], cf[i][j]);
        }
    }

    __syncthreads();
#pragma unroll
    for (int i = 0; i < 2; ++i)
#pragma unroll
        for (int j = 0; j < 2; ++j)
            wx::store_matrix_sync(gates + (wm0 + i * 16) * LDG + wn0 + j * 16,
                                  cf[i][j], LDG, wx::mem_row_major);
    __syncthreads();
}

__global__ void __launch_bounds__(256) fc_kernel(const float* __restrict__ bfc,
                                                 float* __restrict__ out) {
    extern __shared__ __half smh[];
    float* gates = (float*)smh;
    size_t n0 = (size_t)blockIdx.x * 64;
    size_t m0 = (size_t)blockIdx.y * 128;

    gemm16_fc(g_h, m0, g_Wfc, n0, smh, gates);

    const int tid = (int)threadIdx.x;
    const int cg = tid & 3;
    const int rr = tid >> 2;
#pragma unroll
    for (int p = 0; p < 2; ++p) {
        int r = rr + p * 64;
        size_t m = m0 + r;
#pragma unroll
        for (int q = 0; q < 4; ++q) {
            int c = cg * 16 + q * 4;
            float4 gv = *(const float4*)(gates + r * LDG + c);
            float4 bv = *(const float4*)(bfc + n0 + c);
            gv.x += bv.x; gv.y += bv.y; gv.z += bv.z; gv.w += bv.w;
            *(float4*)(out + m * DD + n0 + c) = gv;
        }
    }
}

// ---------------- launch ----------------
extern "C" void kernel_launch(void* const* d_in, const int* in_sizes, int n_in,
                              void* d_out, int out_size) {
    const float* hT  = (const float*)d_in[0];
    // d_in[1] = t (int32) — fixed 128 for this problem
    const float* Wih = (const float*)d_in[2];
    const float* Whh = (const float*)d_in[3];
    const float* bih = (const float*)d_in[4];
    const float* bhh = (const float*)d_in[5];
    const float* Wfc = (const float*)d_in[6];
    const float* bfc = (const float*)d_in[7];
    float* out = (float*)d_out;

    cudaFuncSetAttribute(lstm_persist, cudaFuncAttributeMaxDynamicSharedMemorySize, PERS_SMEM);
    cudaFuncSetAttribute(fc_kernel, cudaFuncAttributeMaxDynamicSharedMemorySize, FC_SMEM);

    prep_kernel<<<(4096 * HD) / 256, 256>>>(Wih, Whh, bih, bhh, Wfc, hT);

    lstm_persist<<<dim3(64, 2), NTHR, PERS_SMEM>>>();

    fc_kernel<<<dim3(4, 256), 256, FC_SMEM>>>(bfc, out);
}